// round 9
// baseline (speedup 1.0000x reference)
#include <cuda_runtime.h>
#include <cuda_fp16.h>
#include <cstdint>

namespace {

constexpr int B = 2, N = 4096, D = 256, R = 64;
constexpr int TM = 64;         // n-rows per block
constexpr int TN = 64;         // m-tile
constexpr int THREADS = 512;   // 16 warps

// prop smem layout in uint32 units; stride 40 (mod 32 == 8) conflict-free.
constexpr int OFE0  = 0;                     // 64 x 40, E double-buffered
constexpr int OFE1  = OFE0 + 64 * 40;
constexpr int OFK0  = OFE1 + 64 * 40;        // 64 x 40
constexpr int OFK1  = OFK0 + 64 * 40;
constexpr int OFV0  = OFK1 + 64 * 40;        // 256 x 40
constexpr int OFV1  = OFV0 + 256 * 40;
constexpr int OFST0 = OFV1 + 256 * 40;       // 64 (floats)
constexpr int OFST1 = OFST0 + 64;
constexpr int OFRD  = OFST1 + 64;            // 256 (floats)
constexpr int SMEM_U32 = OFRD + 256;
constexpr int SMEM_BYTES = SMEM_U32 * 4;     // ~121.5 KB -> 1 block/SM

// qk smem: W transposed [64 cols][260] + one 32-row v batch
constexpr int SW = 260;
constexpr int QK_SMEM = (64 * SW + 32 * D) * 4;   // ~99.3 KB -> 2 blocks/SM? (smem-capped)

// fp16 pair-packed globals (uint32 = half2 = 2 adjacent k/m entries)
__device__ uint32_t g_q[B * N * (R / 2)];      // pair-slot permuted
__device__ uint32_t g_k[B * N * (R / 2)];      // pair-slot permuted
__device__ uint32_t g_vt[B * D * (N / 2)];     // [b][d][m-pair], permuted

typedef unsigned long long ull;

// per-8-pair-group slot permutation: pair l -> slot (l&3)*2 + (l>>2)
__host__ __device__ __forceinline__ int kslot(int p) {
    return (p & ~7) | (((p & 3) << 1) | ((p & 7) >> 2));
}

__device__ __forceinline__ uint32_t pack_h2(float lo, float hi) {
    __half2 h = __floats2half2_rn(lo, hi);
    return *reinterpret_cast<uint32_t*>(&h);
}

__device__ __forceinline__ void unpack2(ull v, float& lo, float& hi) {
    asm("mov.b64 {%0, %1}, %2;" : "=f"(lo), "=f"(hi) : "l"(v));
}
__device__ __forceinline__ void fma2(ull& d, ull a, ull b) {
    asm("fma.rn.f32x2 %0, %1, %2, %0;" : "+l"(d) : "l"(a), "l"(b));
}

__device__ __forceinline__ uint32_t smem_u32p(const void* p) {
    uint32_t a;
    asm("{ .reg .u64 t; cvta.to.shared.u64 t, %1; cvt.u32.u64 %0, t; }" : "=r"(a) : "l"(p));
    return a;
}

__device__ __forceinline__ void cp16(uint32_t dst, const void* src) {
    asm volatile("cp.async.cg.shared.global [%0], [%1], 16;" :: "r"(dst), "l"(src));
}
__device__ __forceinline__ void cp_commit() { asm volatile("cp.async.commit_group;"); }
__device__ __forceinline__ void cp_wait0()  { asm volatile("cp.async.wait_group 0;"); }
__device__ __forceinline__ void cp_wait1()  { asm volatile("cp.async.wait_group 1;"); }

// m16n8k16 f16 MMA, f32 accumulate
__device__ __forceinline__ void mma_f16(float (&d)[4], const uint32_t (&a)[4],
                                        uint32_t b0, uint32_t b1) {
    asm volatile(
        "mma.sync.aligned.m16n8k16.row.col.f32.f16.f16.f32 "
        "{%0,%1,%2,%3}, {%4,%5,%6,%7}, {%8,%9}, {%0,%1,%2,%3};"
        : "+f"(d[0]), "+f"(d[1]), "+f"(d[2]), "+f"(d[3])
        : "r"(a[0]), "r"(a[1]), "r"(a[2]), "r"(a[3]), "r"(b0), "r"(b1));
}

// ---------------------------------------------------------------------------
// Kernel 1: q = val@Wq, k = val@Wk -> fp16 pairs, pair-slot permuted.
// 32 rows/block (grid 512), W transposed in smem, FFMA2 even/odd-d split.
// ---------------------------------------------------------------------------
__global__ void __launch_bounds__(256) qk_kernel(const float* __restrict__ val,
                                                 const float* __restrict__ Wq,
                                                 const float* __restrict__ Wk) {
    extern __shared__ float qsm[];
    float* W_sm = qsm;                     // 64 cols x SW (transposed)
    float* v_sm = qsm + 64 * SW;           // 32 x 256
    const uint32_t vbase = smem_u32p(qsm) + 64 * SW * 4;

    const int t = threadIdx.x;
    const int which = blockIdx.x & 1;
    const int row0 = (blockIdx.x >> 1) * 32;

    const float* __restrict__ W = which ? Wk : Wq;
    uint32_t* __restrict__ out = which ? g_k : g_q;

    // v batch via cp.async (overlaps W transpose staging)
    {
        const float* src = val + (size_t)row0 * D;
#pragma unroll
        for (int i = 0; i < 8; ++i)
            cp16(vbase + (uint32_t)(t + i * 256) * 16u, src + 4 * (t + i * 256));
        cp_commit();
    }
    // stage W transposed: W_sm[c][d] = W[d][c]
    {
        const float4* wsrc = reinterpret_cast<const float4*>(W);
#pragma unroll
        for (int i = 0; i < 16; ++i) {
            int idx = t + i * 256;           // 4096 float4
            int d = idx >> 4, c4 = idx & 15;
            float4 w = wsrc[idx];
            W_sm[(4 * c4 + 0) * SW + d] = w.x;
            W_sm[(4 * c4 + 1) * SW + d] = w.y;
            W_sm[(4 * c4 + 2) * SW + d] = w.z;
            W_sm[(4 * c4 + 3) * SW + d] = w.w;
        }
    }
    cp_wait0();
    __syncthreads();

    const int c  = t & 31;                 // col pair (2c, 2c+1)
    const int rg = t >> 5;                 // rows rg*4 + {0..3}
    const int slot = kslot(c);

    const ulonglong2* wa = reinterpret_cast<const ulonglong2*>(&W_sm[(2 * c) * SW]);
    const ulonglong2* wb = reinterpret_cast<const ulonglong2*>(&W_sm[(2 * c + 1) * SW]);

    ull acc[4][2];
#pragma unroll
    for (int j = 0; j < 4; ++j) { acc[j][0] = 0ull; acc[j][1] = 0ull; }

#pragma unroll 4
    for (int d4 = 0; d4 < 64; ++d4) {
        ulonglong2 wav = wa[d4];
        ulonglong2 wbv = wb[d4];
#pragma unroll
        for (int j = 0; j < 4; ++j) {
            ulonglong2 vv = *reinterpret_cast<const ulonglong2*>(
                &v_sm[(rg * 4 + j) * D + 4 * d4]);
            fma2(acc[j][0], vv.x, wav.x);
            fma2(acc[j][0], vv.y, wav.y);
            fma2(acc[j][1], vv.x, wbv.x);
            fma2(acc[j][1], vv.y, wbv.y);
        }
    }

#pragma unroll
    for (int j = 0; j < 4; ++j) {
        float lo, hi;
        unpack2(acc[j][0], lo, hi); float a0 = lo + hi;
        unpack2(acc[j][1], lo, hi); float a1 = lo + hi;
        out[(size_t)(row0 + rg * 4 + j) * 32 + slot] = pack_h2(a0, a1);
    }
}

// ---------------------------------------------------------------------------
// Kernel 1b: g_vt[b][d][m-pair slot] = half2(val[m], val[m+1]), permuted.
// ---------------------------------------------------------------------------
__global__ void __launch_bounds__(256) vt_kernel(const float* __restrict__ val) {
    __shared__ float tile[64 * 65];
    const int b = blockIdx.z, m0 = blockIdx.x * 64, d0 = blockIdx.y * 64;
    const int t = threadIdx.x;

#pragma unroll
    for (int it = 0; it < 4; ++it) {
        int p = t + it * 256;
        int row = p >> 4, c4 = p & 15;
        float4 v = *reinterpret_cast<const float4*>(
            val + ((size_t)b * N + m0 + row) * D + d0 + 4 * c4);
        tile[(4 * c4 + 0) * 65 + row] = v.x;
        tile[(4 * c4 + 1) * 65 + row] = v.y;
        tile[(4 * c4 + 2) * 65 + row] = v.z;
        tile[(4 * c4 + 3) * 65 + row] = v.w;
    }
    __syncthreads();

#pragma unroll
    for (int it = 0; it < 4; ++it) {
        int p = t + it * 256;
        int drow = p >> 4, j = p & 15;
        int grp = j >> 2, jj = j & 3;
        int mb = grp * 16;
        const float* tr = &tile[drow * 65];
        uint2 o;
        o.x = pack_h2(tr[mb + 2 * jj],     tr[mb + 2 * jj + 1]);
        o.y = pack_h2(tr[mb + 2 * jj + 8], tr[mb + 2 * jj + 9]);
        *reinterpret_cast<uint2*>(
            &g_vt[((size_t)b * D + d0 + drow) * (N / 2) + m0 / 2 + 2 * j]) = o;
    }
}

// ---------------------------------------------------------------------------
// Kernel 2: fused scores -> softsign -> (edges@state, edges@val), fp16 MMA.
// Single-barrier pipeline: iter i runs MMA1(i+1) and MMA2(i); E double-buffered.
// ---------------------------------------------------------------------------
__global__ void __launch_bounds__(THREADS) prop_kernel(const float* __restrict__ state,
                                                       float* __restrict__ out_ds,
                                                       float* __restrict__ out_dv) {
    extern __shared__ float smf[];
    uint32_t* sm = reinterpret_cast<uint32_t*>(smf);
    const uint32_t sbase = smem_u32p(smf);

    const int b  = blockIdx.y;
    const int n0 = blockIdx.x * TM;
    const int t  = threadIdx.x;
    const int wid = t >> 5, lane = t & 31;
    const int g = lane >> 2, tg = lane & 3;
    const int wr = wid & 3, wc = wid >> 2;

    const uint32_t* gk_b  = g_k + (size_t)b * N * 32;
    const uint32_t* gvt_b = g_vt + (size_t)b * D * (N / 2);
    const float* st_b = state + (size_t)b * N;

    auto prefetchK = [&](int m0, int buf) {
        const int ofk = buf ? OFK1 : OFK0;
        int row = t >> 3, cc = t & 7;
        cp16(sbase + (uint32_t)(ofk + row * 40 + 4 * cc) * 4u,
             gk_b + (size_t)(m0 + row) * 32 + 4 * cc);
    };
    auto prefetchV = [&](int m0, int buf) {
        const int ofv = buf ? OFV1 : OFV0;
#pragma unroll
        for (int it = 0; it < 4; ++it) {
            int p = t + it * THREADS;
            int row = p >> 3, cc = p & 7;
            cp16(sbase + (uint32_t)(ofv + row * 40 + 4 * cc) * 4u,
                 gvt_b + (size_t)row * (N / 2) + m0 / 2 + 4 * cc);
        }
    };
    auto prefetchST = [&](int m0, int buf) {
        const int ofst = buf ? OFST1 : OFST0;
        if (t < 16)
            cp16(sbase + (uint32_t)(ofst + 4 * t) * 4u, st_b + m0 + 4 * t);
    };

    // ---- prologue prefetch: group A = {K0, st0}; group B = {K1, VT0, st1}
    prefetchK(0, 0); prefetchST(0, 0); cp_commit();
    prefetchK(TN, 1); prefetchV(0, 0); prefetchST(TN, 1); cp_commit();

    // ---- Q A-fragments from permuted global (one-time): 4 k16-steps
    uint32_t aq[4][4];
    {
        const uint32_t* q0 = g_q + ((size_t)b * N + n0 + 16 * wr + g) * 32;
        const uint32_t* q1 = q0 + 8 * 32;
#pragma unroll
        for (int ks = 0; ks < 4; ++ks) {
            uint2 u0 = *reinterpret_cast<const uint2*>(&q0[8 * ks + 2 * tg]);
            uint2 u1 = *reinterpret_cast<const uint2*>(&q1[8 * ks + 2 * tg]);
            aq[ks][0] = u0.x; aq[ks][1] = u1.x; aq[ks][2] = u0.y; aq[ks][3] = u1.y;
        }
    }

    const int eslot0 = kslot(8 * wc + tg);
    const int eslot1 = kslot(8 * wc + 4 + tg);

    float dv[8][4];
#pragma unroll
    for (int nt = 0; nt < 8; ++nt)
#pragma unroll
        for (int j = 0; j < 4; ++j) dv[nt][j] = 0.f;
    float ds0 = 0.f, ds1 = 0.f;

    // MMA1(tile) + softsign + E store into buf (tile&1); accumulates ds.
    auto mma1_soft = [&](int tilebuf) {
        const int ofk  = tilebuf ? OFK1 : OFK0;
        const int ofst = tilebuf ? OFST1 : OFST0;
        const int ofe  = tilebuf ? OFE1 : OFE0;

        float sacc[2][4];
#pragma unroll
        for (int nt = 0; nt < 2; ++nt)
#pragma unroll
            for (int j = 0; j < 4; ++j) sacc[nt][j] = 0.f;

#pragma unroll
        for (int ks = 0; ks < 4; ++ks) {
#pragma unroll
            for (int nt = 0; nt < 2; ++nt) {
                uint2 bb = *reinterpret_cast<const uint2*>(
                    &sm[ofk + (16 * wc + 8 * nt + g) * 40 + 8 * ks + 2 * tg]);
                mma_f16(sacc[nt], aq[ks], bb.x, bb.y);
            }
        }

#pragma unroll
        for (int nt = 0; nt < 2; ++nt) {
            const int c0 = 16 * wc + 8 * nt + 2 * tg;
            float e00 = __fdividef(sacc[nt][0], 1.f + fabsf(sacc[nt][0]));
            float e01 = __fdividef(sacc[nt][1], 1.f + fabsf(sacc[nt][1]));
            float e10 = __fdividef(sacc[nt][2], 1.f + fabsf(sacc[nt][2]));
            float e11 = __fdividef(sacc[nt][3], 1.f + fabsf(sacc[nt][3]));
            float s0 = smf[ofst + c0], s1 = smf[ofst + c0 + 1];
            ds0 = fmaf(e00, s0, fmaf(e01, s1, ds0));
            ds1 = fmaf(e10, s0, fmaf(e11, s1, ds1));
            const int es = nt ? eslot1 : eslot0;
            sm[ofe + (16 * wr + g) * 40 + es]     = pack_h2(e00, e01);
            sm[ofe + (16 * wr + g + 8) * 40 + es] = pack_h2(e10, e11);
        }
    };

    auto mma2 = [&](int tilebuf) {
        const int ofe = tilebuf ? OFE1 : OFE0;
        const int ofv = tilebuf ? OFV1 : OFV0;
#pragma unroll
        for (int ks = 0; ks < 4; ++ks) {
            uint2 A0 = *reinterpret_cast<const uint2*>(
                &sm[ofe + (16 * wr + g) * 40 + 8 * ks + 2 * tg]);
            uint2 A1 = *reinterpret_cast<const uint2*>(
                &sm[ofe + (16 * wr + g + 8) * 40 + 8 * ks + 2 * tg]);
            uint32_t a[4] = {A0.x, A1.x, A0.y, A1.y};
#pragma unroll
            for (int nt = 0; nt < 8; ++nt) {
                uint2 bb = *reinterpret_cast<const uint2*>(
                    &sm[ofv + (64 * wc + 8 * nt + g) * 40 + 8 * ks + 2 * tg]);
                mma_f16(dv[nt], a, bb.x, bb.y);
            }
        }
    };

    // ---- prologue compute: MMA1 tile 0 (needs group A only)
    cp_wait1();
    __syncthreads();
    mma1_soft(0);

    // ---- main loop: one barrier per tile
#pragma unroll 1
    for (int i = 0; i < N / TN; ++i) {
        cp_wait0();
        __syncthreads();   // tile data (K(i+1), VT(i), st(i+1)) resident; E(i) visible

        if (i + 2 < N / TN) { prefetchK((i + 2) * TN, i & 1); prefetchST((i + 2) * TN, i & 1); }
        if (i + 1 < N / TN) { prefetchV((i + 1) * TN, (i + 1) & 1); }
        cp_commit();

        if (i + 1 < N / TN) mma1_soft((i + 1) & 1);
        mma2(i & 1);
    }

    // ---- epilogue: DV writes
    {
        const int rowA = n0 + 16 * wr + g;
        float* dA = out_dv + ((size_t)b * N + rowA) * D;
        float* dB = dA + 8 * D;
#pragma unroll
        for (int nt = 0; nt < 8; ++nt) {
            const int col = 64 * wc + 8 * nt + 2 * tg;
            *reinterpret_cast<float2*>(dA + col) = make_float2(dv[nt][0], dv[nt][1]);
            *reinterpret_cast<float2*>(dB + col) = make_float2(dv[nt][2], dv[nt][3]);
        }
    }

    // ---- delta_state reduction
    ds0 += __shfl_xor_sync(0xFFFFFFFF, ds0, 1);
    ds0 += __shfl_xor_sync(0xFFFFFFFF, ds0, 2);
    ds1 += __shfl_xor_sync(0xFFFFFFFF, ds1, 1);
    ds1 += __shfl_xor_sync(0xFFFFFFFF, ds1, 2);
    __syncthreads();
    if (tg == 0) {
        smf[OFRD + (16 * wr + g) * 4 + wc]     = ds0;
        smf[OFRD + (16 * wr + g + 8) * 4 + wc] = ds1;
    }
    __syncthreads();
    if (t < TM)
        out_ds[b * N + n0 + t] = (smf[OFRD + t * 4] + smf[OFRD + t * 4 + 1]) +
                                 (smf[OFRD + t * 4 + 2] + smf[OFRD + t * 4 + 3]);
}

}  // namespace

extern "C" void kernel_launch(void* const* d_in, const int* in_sizes, int n_in,
                              void* d_out, int out_size) {
    const float* state = (const float*)d_in[0];   // [B, N]
    const float* val   = (const float*)d_in[1];   // [B, N, D]
    const float* Wq    = (const float*)d_in[2];   // [D, R]
    const float* Wk    = (const float*)d_in[3];   // [D, R]

    float* out_ds = (float*)d_out;                // [B, N]
    float* out_dv = out_ds + B * N;               // [B, N, D]

    cudaFuncSetAttribute(qk_kernel, cudaFuncAttributeMaxDynamicSharedMemorySize, QK_SMEM);
    cudaFuncSetAttribute(prop_kernel, cudaFuncAttributeMaxDynamicSharedMemorySize, SMEM_BYTES);

    qk_kernel<<<(B * N / 32) * 2, 256, QK_SMEM>>>(val, Wq, Wk);
    vt_kernel<<<dim3(N / 64, D / 64, B), 256>>>(val);
    prop_kernel<<<dim3(N / TM, B), THREADS, SMEM_BYTES>>>(state, out_ds, out_dv);
}

// round 10
// speedup vs baseline: 1.1279x; 1.1279x over previous
#include <cuda_runtime.h>
#include <cuda_fp16.h>
#include <cstdint>

namespace {

constexpr int B = 2, N = 4096, D = 256, R = 64;
constexpr int TM = 64;         // n-rows per block
constexpr int TN = 64;         // m-tile
constexpr int THREADS = 512;   // 16 warps

// prop smem layout in uint32 units; stride 40 (mod 32 == 8) conflict-free.
constexpr int OFE   = 0;                     // 64 x 40 (32 pair-cols used)
constexpr int OFK0  = OFE + 64 * 40;         // 64 x 40
constexpr int OFK1  = OFK0 + 64 * 40;
constexpr int OFV0  = OFK1 + 64 * 40;        // 256 x 40
constexpr int OFV1  = OFV0 + 256 * 40;
constexpr int OFST0 = OFV1 + 256 * 40;       // 64 (floats)
constexpr int OFST1 = OFST0 + 64;
constexpr int OFRD  = OFST1 + 64;            // 256 (floats)
constexpr int SMEM_U32 = OFRD + 256;
constexpr int SMEM_BYTES = SMEM_U32 * 4;     // ~111.6 KB -> 1 block/SM

// merged prep kernel
constexpr int PREP_QK_BLOCKS = B * N / 32;           // 256 (32 rows each, q AND k)
constexpr int PREP_VT_BLOCKS = (N / 64) * (D / 64) * B;   // 512
constexpr int PREP_SMEM = 32 * D * 4;                // 32KB (vt needs 64*65*4=16.6KB)

// fp16 pair-packed globals (uint32 = half2 = 2 adjacent k/m entries)
__device__ uint32_t g_q[B * N * (R / 2)];      // pair-slot permuted
__device__ uint32_t g_k[B * N * (R / 2)];      // pair-slot permuted
__device__ uint32_t g_vt[B * D * (N / 2)];     // [b][d][m-pair], permuted

typedef unsigned long long ull;

// per-8-pair-group slot permutation: pair l -> slot (l&3)*2 + (l>>2)
__host__ __device__ __forceinline__ int kslot(int p) {
    return (p & ~7) | (((p & 3) << 1) | ((p & 7) >> 2));
}

__device__ __forceinline__ uint32_t pack_h2(float lo, float hi) {
    __half2 h = __floats2half2_rn(lo, hi);
    return *reinterpret_cast<uint32_t*>(&h);
}

__device__ __forceinline__ ull bcast2(float v) {
    ull r;
    asm("mov.b64 %0, {%1, %1};" : "=l"(r) : "f"(v));
    return r;
}
__device__ __forceinline__ void unpack2(ull v, float& lo, float& hi) {
    asm("mov.b64 {%0, %1}, %2;" : "=f"(lo), "=f"(hi) : "l"(v));
}
__device__ __forceinline__ void fma2(ull& d, ull a, ull b) {
    asm("fma.rn.f32x2 %0, %1, %2, %0;" : "+l"(d) : "l"(a), "l"(b));
}

__device__ __forceinline__ uint32_t smem_u32p(const void* p) {
    uint32_t a;
    asm("{ .reg .u64 t; cvta.to.shared.u64 t, %1; cvt.u32.u64 %0, t; }" : "=r"(a) : "l"(p));
    return a;
}

__device__ __forceinline__ void cp16(uint32_t dst, const void* src) {
    asm volatile("cp.async.cg.shared.global [%0], [%1], 16;" :: "r"(dst), "l"(src));
}
__device__ __forceinline__ void cp_commit() { asm volatile("cp.async.commit_group;"); }
__device__ __forceinline__ void cp_wait0()  { asm volatile("cp.async.wait_group 0;"); }

// m16n8k16 f16 MMA, f32 accumulate
__device__ __forceinline__ void mma_f16(float (&d)[4], const uint32_t (&a)[4],
                                        uint32_t b0, uint32_t b1) {
    asm volatile(
        "mma.sync.aligned.m16n8k16.row.col.f32.f16.f16.f32 "
        "{%0,%1,%2,%3}, {%4,%5,%6,%7}, {%8,%9}, {%0,%1,%2,%3};"
        : "+f"(d[0]), "+f"(d[1]), "+f"(d[2]), "+f"(d[3])
        : "r"(a[0]), "r"(a[1]), "r"(a[2]), "r"(a[3]), "r"(b0), "r"(b1));
}

// ---------------------------------------------------------------------------
// Merged prep kernel: blocks [0,256) do q+k projection (32 rows each, W from
// L1, packed FFMA2); blocks [256,768) do the vt transpose/pack.
// ---------------------------------------------------------------------------
__global__ void __launch_bounds__(256) prep_kernel(const float* __restrict__ val,
                                                   const float* __restrict__ Wq,
                                                   const float* __restrict__ Wk) {
    extern __shared__ float ps[];
    const int t = threadIdx.x;

    if (blockIdx.x < PREP_QK_BLOCKS) {
        // ---------------- q/k projection ----------------
        const int row0 = blockIdx.x * 32;
        const uint32_t vbase = smem_u32p(ps);

        {
            const float* src = val + (size_t)row0 * D;
#pragma unroll
            for (int i = 0; i < 8; ++i)
                cp16(vbase + (uint32_t)(t + i * 256) * 16u, src + 4 * (t + i * 256));
            cp_commit();
        }
        cp_wait0();
        __syncthreads();

        const int c  = t & 31;               // col pair (2c, 2c+1)
        const int rg = t >> 5;               // rows rg*4 + {0..3}
        const int slot = kslot(c);

        const ull* __restrict__ wqp = reinterpret_cast<const ull*>(Wq) + c;
        const ull* __restrict__ wkp = reinterpret_cast<const ull*>(Wk) + c;

        ull aq[4], ak[4];
#pragma unroll
        for (int j = 0; j < 4; ++j) { aq[j] = 0ull; ak[j] = 0ull; }

#pragma unroll 4
        for (int d = 0; d < D; ++d) {
            ull wq2 = __ldg(wqp + d * 32);
            ull wk2 = __ldg(wkp + d * 32);
#pragma unroll
            for (int j = 0; j < 4; ++j) {
                ull vb = bcast2(ps[(rg * 4 + j) * D + d]);
                fma2(aq[j], vb, wq2);
                fma2(ak[j], vb, wk2);
            }
        }

#pragma unroll
        for (int j = 0; j < 4; ++j) {
            const size_t base = (size_t)(row0 + rg * 4 + j) * 32;
            float lo, hi;
            unpack2(aq[j], lo, hi);
            g_q[base + slot] = pack_h2(lo, hi);
            unpack2(ak[j], lo, hi);
            g_k[base + slot] = pack_h2(lo, hi);
        }
    } else {
        // ---------------- vt transpose/pack ----------------
        const int idx = blockIdx.x - PREP_QK_BLOCKS;
        const int m0 = (idx & 63) * 64;
        const int d0 = ((idx >> 6) & 3) * 64;
        const int b  = idx >> 8;
        float* tile = ps;                    // 64 x 65

#pragma unroll
        for (int it = 0; it < 4; ++it) {
            int p = t + it * 256;
            int row = p >> 4, c4 = p & 15;
            float4 v = *reinterpret_cast<const float4*>(
                val + ((size_t)b * N + m0 + row) * D + d0 + 4 * c4);
            tile[(4 * c4 + 0) * 65 + row] = v.x;
            tile[(4 * c4 + 1) * 65 + row] = v.y;
            tile[(4 * c4 + 2) * 65 + row] = v.z;
            tile[(4 * c4 + 3) * 65 + row] = v.w;
        }
        __syncthreads();

#pragma unroll
        for (int it = 0; it < 4; ++it) {
            int p = t + it * 256;
            int drow = p >> 4, j = p & 15;
            int grp = j >> 2, jj = j & 3;
            int mb = grp * 16;
            const float* tr = &tile[drow * 65];
            uint2 o;
            o.x = pack_h2(tr[mb + 2 * jj],     tr[mb + 2 * jj + 1]);
            o.y = pack_h2(tr[mb + 2 * jj + 8], tr[mb + 2 * jj + 9]);
            *reinterpret_cast<uint2*>(
                &g_vt[((size_t)b * D + d0 + drow) * (N / 2) + m0 / 2 + 2 * j]) = o;
        }
    }
}

// ---------------------------------------------------------------------------
// Kernel 2: fused scores -> softsign -> (edges@state, edges@val), fp16 MMA.
// (round-8 version, verbatim: TN=64 tiles, 2 barriers/tile — measured 93us)
// ---------------------------------------------------------------------------
__global__ void __launch_bounds__(THREADS) prop_kernel(const float* __restrict__ state,
                                                       float* __restrict__ out_ds,
                                                       float* __restrict__ out_dv) {
    extern __shared__ float smf[];
    uint32_t* sm = reinterpret_cast<uint32_t*>(smf);
    const uint32_t sbase = smem_u32p(smf);

    const int b  = blockIdx.y;
    const int n0 = blockIdx.x * TM;
    const int t  = threadIdx.x;
    const int wid = t >> 5, lane = t & 31;
    const int g = lane >> 2, tg = lane & 3;
    const int wr = wid & 3, wc = wid >> 2;

    const uint32_t* gk_b  = g_k + (size_t)b * N * 32;
    const uint32_t* gvt_b = g_vt + (size_t)b * D * (N / 2);
    const float* st_b = state + (size_t)b * N;

    auto prefetch = [&](int m0, int buf) {
        const int ofk  = buf ? OFK1 : OFK0;
        const int ofv  = buf ? OFV1 : OFV0;
        const int ofst = buf ? OFST1 : OFST0;
        {   // K tile: 64 rows x 8 uint4
            int row = t >> 3, cc = t & 7;
            cp16(sbase + (uint32_t)(ofk + row * 40 + 4 * cc) * 4u,
                 gk_b + (size_t)(m0 + row) * 32 + 4 * cc);
        }
#pragma unroll
        for (int it = 0; it < 4; ++it) {   // VT: 256 rows x 8 uint4
            int p = t + it * THREADS;
            int row = p >> 3, cc = p & 7;
            cp16(sbase + (uint32_t)(ofv + row * 40 + 4 * cc) * 4u,
                 gvt_b + (size_t)row * (N / 2) + m0 / 2 + 4 * cc);
        }
        if (t < 16)
            cp16(sbase + (uint32_t)(ofst + 4 * t) * 4u, st_b + m0 + 4 * t);
    };

    prefetch(0, 0);
    cp_commit();

    // ---- Q A-fragments from permuted global (one-time): 4 k16-steps
    uint32_t aq[4][4];
    {
        const uint32_t* q0 = g_q + ((size_t)b * N + n0 + 16 * wr + g) * 32;
        const uint32_t* q1 = q0 + 8 * 32;
#pragma unroll
        for (int ks = 0; ks < 4; ++ks) {
            uint2 u0 = *reinterpret_cast<const uint2*>(&q0[8 * ks + 2 * tg]);
            uint2 u1 = *reinterpret_cast<const uint2*>(&q1[8 * ks + 2 * tg]);
            aq[ks][0] = u0.x; aq[ks][1] = u1.x; aq[ks][2] = u0.y; aq[ks][3] = u1.y;
        }
    }

    const int eslot0 = kslot(8 * wc + tg);
    const int eslot1 = kslot(8 * wc + 4 + tg);

    float dv[8][4];
#pragma unroll
    for (int nt = 0; nt < 8; ++nt)
#pragma unroll
        for (int j = 0; j < 4; ++j) dv[nt][j] = 0.f;
    float ds0 = 0.f, ds1 = 0.f;

#pragma unroll 1
    for (int i = 0; i < N / TN; ++i) {
        const int buf = i & 1;
        const int ofk  = buf ? OFK1 : OFK0;
        const int ofv  = buf ? OFV1 : OFV0;
        const int ofst = buf ? OFST1 : OFST0;

        cp_wait0();
        __syncthreads();

        if (i + 1 < N / TN) {
            prefetch((i + 1) * TN, buf ^ 1);
            cp_commit();
        }

        // ---- MMA1: S(16x16 per warp) = Q . K^T  (R=64 -> 4 k16 steps, 2 n8)
        float sacc[2][4];
#pragma unroll
        for (int nt = 0; nt < 2; ++nt)
#pragma unroll
            for (int j = 0; j < 4; ++j) sacc[nt][j] = 0.f;

#pragma unroll
        for (int ks = 0; ks < 4; ++ks) {
#pragma unroll
            for (int nt = 0; nt < 2; ++nt) {
                uint2 bb = *reinterpret_cast<const uint2*>(
                    &sm[ofk + (16 * wc + 8 * nt + g) * 40 + 8 * ks + 2 * tg]);
                mma_f16(sacc[nt], aq[ks], bb.x, bb.y);
            }
        }

        // ---- softsign + delta_state + E(fp16 pairs, permuted slots)
#pragma unroll
        for (int nt = 0; nt < 2; ++nt) {
            const int c0 = 16 * wc + 8 * nt + 2 * tg;
            float e00 = __fdividef(sacc[nt][0], 1.f + fabsf(sacc[nt][0]));
            float e01 = __fdividef(sacc[nt][1], 1.f + fabsf(sacc[nt][1]));
            float e10 = __fdividef(sacc[nt][2], 1.f + fabsf(sacc[nt][2]));
            float e11 = __fdividef(sacc[nt][3], 1.f + fabsf(sacc[nt][3]));
            float s0 = smf[ofst + c0], s1 = smf[ofst + c0 + 1];
            ds0 = fmaf(e00, s0, fmaf(e01, s1, ds0));
            ds1 = fmaf(e10, s0, fmaf(e11, s1, ds1));
            const int es = nt ? eslot1 : eslot0;
            sm[OFE + (16 * wr + g) * 40 + es]     = pack_h2(e00, e01);
            sm[OFE + (16 * wr + g + 8) * 40 + es] = pack_h2(e10, e11);
        }
        __syncthreads();

        // ---- MMA2: DV(16x64 per warp) += E . V  (k=64 -> 4 k16 steps)
#pragma unroll
        for (int ks = 0; ks < 4; ++ks) {
            uint2 A0 = *reinterpret_cast<const uint2*>(
                &sm[OFE + (16 * wr + g) * 40 + 8 * ks + 2 * tg]);
            uint2 A1 = *reinterpret_cast<const uint2*>(
                &sm[OFE + (16 * wr + g + 8) * 40 + 8 * ks + 2 * tg]);
            uint32_t a[4] = {A0.x, A1.x, A0.y, A1.y};
#pragma unroll
            for (int nt = 0; nt < 8; ++nt) {
                uint2 bb = *reinterpret_cast<const uint2*>(
                    &sm[ofv + (64 * wc + 8 * nt + g) * 40 + 8 * ks + 2 * tg]);
                mma_f16(dv[nt], a, bb.x, bb.y);
            }
        }
    }

    // ---- epilogue: DV writes
    {
        const int rowA = n0 + 16 * wr + g;
        float* dA = out_dv + ((size_t)b * N + rowA) * D;
        float* dB = dA + 8 * D;
#pragma unroll
        for (int nt = 0; nt < 8; ++nt) {
            const int col = 64 * wc + 8 * nt + 2 * tg;
            *reinterpret_cast<float2*>(dA + col) = make_float2(dv[nt][0], dv[nt][1]);
            *reinterpret_cast<float2*>(dB + col) = make_float2(dv[nt][2], dv[nt][3]);
        }
    }

    // ---- delta_state reduction (quad shuffle, then 4 wc-partials per row)
    ds0 += __shfl_xor_sync(0xFFFFFFFF, ds0, 1);
    ds0 += __shfl_xor_sync(0xFFFFFFFF, ds0, 2);
    ds1 += __shfl_xor_sync(0xFFFFFFFF, ds1, 1);
    ds1 += __shfl_xor_sync(0xFFFFFFFF, ds1, 2);
    __syncthreads();
    if (tg == 0) {
        smf[OFRD + (16 * wr + g) * 4 + wc]     = ds0;
        smf[OFRD + (16 * wr + g + 8) * 4 + wc] = ds1;
    }
    __syncthreads();
    if (t < TM)
        out_ds[b * N + n0 + t] = (smf[OFRD + t * 4] + smf[OFRD + t * 4 + 1]) +
                                 (smf[OFRD + t * 4 + 2] + smf[OFRD + t * 4 + 3]);
}

}  // namespace

extern "C" void kernel_launch(void* const* d_in, const int* in_sizes, int n_in,
                              void* d_out, int out_size) {
    const float* state = (const float*)d_in[0];   // [B, N]
    const float* val   = (const float*)d_in[1];   // [B, N, D]
    const float* Wq    = (const float*)d_in[2];   // [D, R]
    const float* Wk    = (const float*)d_in[3];   // [D, R]

    float* out_ds = (float*)d_out;                // [B, N]
    float* out_dv = out_ds + B * N;               // [B, N, D]

    cudaFuncSetAttribute(prep_kernel, cudaFuncAttributeMaxDynamicSharedMemorySize, PREP_SMEM);
    cudaFuncSetAttribute(prop_kernel, cudaFuncAttributeMaxDynamicSharedMemorySize, SMEM_BYTES);

    prep_kernel<<<PREP_QK_BLOCKS + PREP_VT_BLOCKS, 256, PREP_SMEM>>>(val, Wq, Wk);
    prop_kernel<<<dim3(N / TM, B), THREADS, SMEM_BYTES>>>(state, out_ds, out_dv);
}